// round 3
// baseline (speedup 1.0000x reference)
#include <cuda_runtime.h>
#include <cuda_bf16.h>

// Problem constants (fixed by the reference):
//   x: (B=8, T=4096, C=3, D=256) fp32, row-major
//   w: (1, 3584, 1, 1) fp32
//   KERNELS = [2,4,8] for every channel; 4096/2 + 4096/4 + 4096/8 = 3584 = MAX_LEN
//   out[b,p,c,d] = avg*w[p] + max*(1-w[p])  ==  max + w[p]*(avg-max)
//
// One pass over input. Each CTA: one (batch, 8-row T-group). 192 threads each
// own one float4 lane of the contiguous 768-float C*D inner dim (192*16B = one
// full row -> perfectly coalesced). Two half-group phases (4 loads each) keep
// MLP_p1 low (B300 cross-CTA L1tex-queue spread model) and overlap stores with
// the second load batch. Streaming hints (__ldcs/__stcs): zero reuse, 189MB
// working set > 126MB L2. w loads vectorized (float4 + float2 + float).

#define B_      8
#define T_      4096
#define CD4_    192          // (3*256)/4 float4 lanes per (b,t) row
#define MAXLEN_ 3584
#define NGRP_   (T_ / 8)     // 512 groups of 8 rows

__device__ __forceinline__ float4 f4add(float4 a, float4 b) {
    return make_float4(a.x + b.x, a.y + b.y, a.z + b.z, a.w + b.w);
}
__device__ __forceinline__ float4 f4max(float4 a, float4 b) {
    return make_float4(fmaxf(a.x, b.x), fmaxf(a.y, b.y),
                       fmaxf(a.z, b.z), fmaxf(a.w, b.w));
}
// out = mx + wv*(s*inv_k - mx)
__device__ __forceinline__ float4 f4blend(float4 s, float inv_k, float4 mx, float wv) {
    float4 r;
    r.x = fmaf(wv, fmaf(s.x, inv_k, -mx.x), mx.x);
    r.y = fmaf(wv, fmaf(s.y, inv_k, -mx.y), mx.y);
    r.z = fmaf(wv, fmaf(s.z, inv_k, -mx.z), mx.z);
    r.w = fmaf(wv, fmaf(s.w, inv_k, -mx.w), mx.w);
    return r;
}

__global__ __launch_bounds__(CD4_, 8)
void multi_scale_pool_kernel(const float4* __restrict__ in,
                             const float*  __restrict__ w,
                             float4*       __restrict__ out)
{
    const int lane = threadIdx.x;        // 0..191
    const int g    = blockIdx.x;         // 0..511 — 8-row group within T
    const int b    = blockIdx.y;         // 0..7

    const float4* src = in + ((size_t)b * T_ + (size_t)g * 8) * CD4_ + lane;
    float4* dst = out + (size_t)b * MAXLEN_ * CD4_ + lane;

    // Output row positions:
    //   k=2: p = g*4 + j        (j=0..3)
    //   k=4: p = 2048 + g*2 + j (j=0..1)
    //   k=8: p = 3072 + g
    const int p2 = g * 4;
    const int p4 = 2048 + g * 2;
    const int p8 = 3072 + g;

    // w broadcast loads, vectorized: p2 = 4g is float4-aligned, p4 is
    // float2-aligned. Uniform across CTA -> L1-hit broadcasts.
    const float4 w2 = __ldg((const float4*)&w[p2]);
    const float2 w4 = __ldg((const float2*)&w[p4]);
    const float  w8 = __ldg(&w[p8]);

    // ---- Phase 1: rows 0..3 ----
    float4 v0 = __ldcs(&src[0 * CD4_]);
    float4 v1 = __ldcs(&src[1 * CD4_]);
    float4 v2 = __ldcs(&src[2 * CD4_]);
    float4 v3 = __ldcs(&src[3 * CD4_]);

    float4 s01 = f4add(v0, v1), m01 = f4max(v0, v1);
    float4 s23 = f4add(v2, v3), m23 = f4max(v2, v3);
    float4 s0123 = f4add(s01, s23), m0123 = f4max(m01, m23);

    __stcs(&dst[(size_t)(p2 + 0) * CD4_], f4blend(s01, 0.5f, m01, w2.x));
    __stcs(&dst[(size_t)(p2 + 1) * CD4_], f4blend(s23, 0.5f, m23, w2.y));

    // ---- Phase 2: rows 4..7 (loads issued under store shadow) ----
    float4 v4 = __ldcs(&src[4 * CD4_]);
    float4 v5 = __ldcs(&src[5 * CD4_]);
    float4 v6 = __ldcs(&src[6 * CD4_]);
    float4 v7 = __ldcs(&src[7 * CD4_]);

    float4 s45 = f4add(v4, v5), m45 = f4max(v4, v5);
    float4 s67 = f4add(v6, v7), m67 = f4max(v6, v7);
    float4 s4567 = f4add(s45, s67), m4567 = f4max(m45, m67);

    __stcs(&dst[(size_t)(p2 + 2) * CD4_], f4blend(s45, 0.5f, m45, w2.z));
    __stcs(&dst[(size_t)(p2 + 3) * CD4_], f4blend(s67, 0.5f, m67, w2.w));

    // ---- Combine: k=4 and k=8 ----
    float4 s8 = f4add(s0123, s4567), m8 = f4max(m0123, m4567);

    __stcs(&dst[(size_t)(p4 + 0) * CD4_], f4blend(s0123, 0.25f, m0123, w4.x));
    __stcs(&dst[(size_t)(p4 + 1) * CD4_], f4blend(s4567, 0.25f, m4567, w4.y));
    __stcs(&dst[(size_t)p8 * CD4_],       f4blend(s8,    0.125f, m8,    w8));
}

extern "C" void kernel_launch(void* const* d_in, const int* in_sizes, int n_in,
                              void* d_out, int out_size)
{
    const float4* x = (const float4*)d_in[0];   // (8,4096,3,256) fp32
    const float*  w = (const float*) d_in[1];   // (1,3584,1,1)  fp32
    float4* out = (float4*)d_out;               // (8,3584,3,256) fp32

    dim3 grid(NGRP_, B_);
    multi_scale_pool_kernel<<<grid, CD4_>>>(x, w, out);
}